// round 12
// baseline (speedup 1.0000x reference)
#include <cuda_runtime.h>
#include <cuda_fp16.h>
#include <cstdint>

// ---------------------------------------------------------------------------
// PingHead on sm_103 (legacy mma.sync path, fp16 operands / fp32 accum).
// gi = x @ W_ih^T : M=65536, N=384, K=1024 ; fused GRU-gate epilogue.
// R12: R11 (2 CTAs/SM, M_TILE=64, 1m x 8n, K64/128B rows) with the copy of
// chunk kc+1 moved into the middle of MMA(kc): A-LDG stall overlaps other
// warps' MMA issue instead of creating a barrier-aligned SMSP-dead window.
// ---------------------------------------------------------------------------

#define M_TILE 64
#define KCHUNKS 16
#define A_ST 8192                            // 64 rows x 128B
#define B_ST 49152                           // 384 rows x 128B
#define STAGE_BYTES (A_ST + B_ST)            // 57344
#define SMEM_DYN (2 * STAGE_BYTES)           // 114688 ; 2 CTAs/SM
#define ROWP 385
// gi (64*385*4 = 98560) fits inside the 114688-byte ring

__device__ __half g_wh[384 * 1024];          // W_ih pre-converted to fp16 (rne)

__device__ __forceinline__ uint32_t smem_u32(const void* p) {
    uint32_t a;
    asm("{ .reg .u64 t; cvta.to.shared.u64 t, %1; cvt.u32.u64 %0, t; }" : "=r"(a) : "l"(p));
    return a;
}

__device__ __forceinline__ void cp_async16(uint32_t dst, const void* src) {
    asm volatile("cp.async.cg.shared.global [%0], [%1], 16;" :: "r"(dst), "l"(src) : "memory");
}
#define CP_COMMIT() asm volatile("cp.async.commit_group;" ::: "memory")
#define CP_WAIT0()  asm volatile("cp.async.wait_group 0;" ::: "memory")

__device__ __forceinline__ void ldsm4(uint32_t* r, uint32_t addr) {
    asm volatile("ldmatrix.sync.aligned.m8n8.x4.shared.b16 {%0,%1,%2,%3}, [%4];"
                 : "=r"(r[0]), "=r"(r[1]), "=r"(r[2]), "=r"(r[3]) : "r"(addr));
}

__device__ __forceinline__ uint32_t pack2h(float a, float b) {
    __half2 h = __floats2half2_rn(a, b);
    return *reinterpret_cast<uint32_t*>(&h);
}

__device__ __forceinline__ void mma_f16(float* d, const uint32_t* a, const uint32_t* b) {
    asm volatile("mma.sync.aligned.m16n8k16.row.col.f32.f16.f16.f32 "
                 "{%0,%1,%2,%3},{%4,%5,%6,%7},{%8,%9},{%0,%1,%2,%3};"
                 : "+f"(d[0]), "+f"(d[1]), "+f"(d[2]), "+f"(d[3])
                 : "r"(a[0]), "r"(a[1]), "r"(a[2]), "r"(a[3]), "r"(b[0]), "r"(b[1]));
}

// --- pre-kernel: W fp32 -> fp16 (rne) ---
__global__ void __launch_bounds__(256) wconv_kernel(const float* __restrict__ w) {
    const int i = (blockIdx.x * 256 + threadIdx.x) * 8;
    const float4 v0 = *reinterpret_cast<const float4*>(w + i);
    const float4 v1 = *reinterpret_cast<const float4*>(w + i + 4);
    uint4 o = make_uint4(pack2h(v0.x, v0.y), pack2h(v0.z, v0.w),
                         pack2h(v1.x, v1.y), pack2h(v1.z, v1.w));
    *reinterpret_cast<uint4*>(g_wh + i) = o;
}

__global__ void __launch_bounds__(256, 2)
ping_head_kernel(const float* __restrict__ x,
                 const float* __restrict__ b_ih,
                 const float* __restrict__ b_hh,
                 const float* __restrict__ lin_w,
                 const float* __restrict__ lin_b,
                 float* __restrict__ out) {
    extern __shared__ char dsm[];

    const int tid = threadIdx.x;
    const int wid = tid >> 5;
    const int lane = tid & 31;
    const int m0 = blockIdx.x * M_TILE;

    const uint32_t sb = smem_u32(dsm);
    char* sb_ptr = dsm;

    const int a_row = tid >> 2;
    const int a_q   = tid & 3;

    // full stage copy (prologue only)
    auto copy_stage = [&](int kc) {
        const int st = kc & 1;
        const int koff = kc * 64;
        const uint32_t bbase = sb + (uint32_t)(st * STAGE_BYTES + A_ST);
#pragma unroll
        for (int ch = 0; ch < 12; ch++) {
            const int bi = tid + ch * 256;
            const int row = bi >> 3, c = bi & 7;
            const uint32_t doff = (uint32_t)(row * 128) +
                                  (((uint32_t)(c * 16)) ^ ((uint32_t)(row & 7) << 4));
            cp_async16(bbase + doff, g_wh + (size_t)row * 1024 + koff + c * 8);
        }
        const float* asrc = x + (size_t)(m0 + a_row) * 1024 + koff + a_q * 16;
        float4 f0 = *reinterpret_cast<const float4*>(asrc);
        float4 f1 = *reinterpret_cast<const float4*>(asrc + 4);
        float4 f2 = *reinterpret_cast<const float4*>(asrc + 8);
        float4 f3 = *reinterpret_cast<const float4*>(asrc + 12);
        char* sA = sb_ptr + st * STAGE_BYTES;
        const uint32_t xr = (uint32_t)((a_row & 7) << 4);
        uint4 o0 = make_uint4(pack2h(f0.x, f0.y), pack2h(f0.z, f0.w),
                              pack2h(f1.x, f1.y), pack2h(f1.z, f1.w));
        uint4 o1 = make_uint4(pack2h(f2.x, f2.y), pack2h(f2.z, f2.w),
                              pack2h(f3.x, f3.y), pack2h(f3.z, f3.w));
        *reinterpret_cast<uint4*>(sA + a_row * 128 + (((uint32_t)(a_q * 32)) ^ xr))      = o0;
        *reinterpret_cast<uint4*>(sA + a_row * 128 + (((uint32_t)(a_q * 32 + 16)) ^ xr)) = o1;
    };

    // ---- ldmatrix addressing: 1m x 8n warp grid, warp tile 64m x 48n ----
    const int nb = wid * 48;

    const int ri = lane & 15;
    const uint32_t sega = (uint32_t)((lane >> 4) << 4);
    const uint32_t xpa  = (uint32_t)((ri & 7) << 4);
    const uint32_t a_root = (uint32_t)(ri * 128);

    const int rb = (lane & 7) + (((lane >> 4) & 1) << 3);
    const uint32_t segb = (uint32_t)(((lane >> 3) & 1) << 4);
    const uint32_t xpb  = (uint32_t)((rb & 7) << 4);
    const uint32_t b_root = (uint32_t)A_ST + (uint32_t)((nb + rb) * 128);

    float acc[4][6][4];
#pragma unroll
    for (int t = 0; t < 4; t++)
#pragma unroll
        for (int j = 0; j < 6; j++)
#pragma unroll
            for (int q = 0; q < 4; q++) acc[t][j][q] = 0.0f;

    copy_stage(0); CP_COMMIT();

#pragma unroll 2
    for (int kc = 0; kc < KCHUNKS; kc++) {
        CP_WAIT0();                       // B(kc) done (only pending group)
        __syncthreads();                  // A(kc) STS visible; ring safe

        const uint32_t stb = sb + (uint32_t)((kc & 1) * STAGE_BYTES);

        // ---- MMA s = 0 ----
        {
            uint32_t af[4][4];
#pragma unroll
            for (int t = 0; t < 4; t++)
                ldsm4(af[t], stb + a_root + (uint32_t)(t * 2048) + ((0u + sega) ^ xpa));
#pragma unroll
            for (int jp = 0; jp < 3; jp++) {
                uint32_t bf[4];
                ldsm4(bf, stb + b_root + (uint32_t)(jp * 2048) + ((0u + segb) ^ xpb));
#pragma unroll
                for (int t = 0; t < 4; t++) {
                    mma_f16(acc[t][2 * jp],     af[t], bf);
                    mma_f16(acc[t][2 * jp + 1], af[t], bf + 2);
                }
            }
        }

        // ---- copy chunk kc+1 (LDG stall overlapped with other warps' MMAs) ----
        if (kc + 1 < KCHUNKS) {
            const int st = (kc + 1) & 1;
            const int koff = (kc + 1) * 64;
            // A LDGs first (earliest start)
            const float* asrc = x + (size_t)(m0 + a_row) * 1024 + koff + a_q * 16;
            float4 f0 = *reinterpret_cast<const float4*>(asrc);
            float4 f1 = *reinterpret_cast<const float4*>(asrc + 4);
            float4 f2 = *reinterpret_cast<const float4*>(asrc + 8);
            float4 f3 = *reinterpret_cast<const float4*>(asrc + 12);
            // B cp.async (independent of LDG returns)
            const uint32_t bbase = sb + (uint32_t)(st * STAGE_BYTES + A_ST);
#pragma unroll
            for (int ch = 0; ch < 12; ch++) {
                const int bi = tid + ch * 256;
                const int row = bi >> 3, c = bi & 7;
                const uint32_t doff = (uint32_t)(row * 128) +
                                      (((uint32_t)(c * 16)) ^ ((uint32_t)(row & 7) << 4));
                cp_async16(bbase + doff, g_wh + (size_t)row * 1024 + koff + c * 8);
            }
            CP_COMMIT();
            // cvt + STS (stalls this warp on LDG return; others keep MMAing)
            char* sA = sb_ptr + st * STAGE_BYTES;
            const uint32_t xr = (uint32_t)((a_row & 7) << 4);
            uint4 o0 = make_uint4(pack2h(f0.x, f0.y), pack2h(f0.z, f0.w),
                                  pack2h(f1.x, f1.y), pack2h(f1.z, f1.w));
            uint4 o1 = make_uint4(pack2h(f2.x, f2.y), pack2h(f2.z, f2.w),
                                  pack2h(f3.x, f3.y), pack2h(f3.z, f3.w));
            *reinterpret_cast<uint4*>(sA + a_row * 128 + (((uint32_t)(a_q * 32)) ^ xr))      = o0;
            *reinterpret_cast<uint4*>(sA + a_row * 128 + (((uint32_t)(a_q * 32 + 16)) ^ xr)) = o1;
        }

        // ---- MMA s = 1..3 ----
#pragma unroll
        for (int s = 1; s < 4; s++) {
            const uint32_t sbytes = (uint32_t)(s * 32);
            uint32_t af[4][4];
#pragma unroll
            for (int t = 0; t < 4; t++)
                ldsm4(af[t], stb + a_root + (uint32_t)(t * 2048) + ((sbytes + sega) ^ xpa));
#pragma unroll
            for (int jp = 0; jp < 3; jp++) {
                uint32_t bf[4];
                ldsm4(bf, stb + b_root + (uint32_t)(jp * 2048) + ((sbytes + segb) ^ xpb));
#pragma unroll
                for (int t = 0; t < 4; t++) {
                    mma_f16(acc[t][2 * jp],     af[t], bf);
                    mma_f16(acc[t][2 * jp + 1], af[t], bf + 2);
                }
            }
        }
        __syncthreads();                  // reads done before buffer rewrite
    }

    // ---- spill gi to smem (64 x ROWP), reusing the ring ----
    float* gi = reinterpret_cast<float*>(sb_ptr);
    {
        const int r0 = lane >> 2;
        const int c0 = nb + 2 * (lane & 3);
#pragma unroll
        for (int t = 0; t < 4; t++) {
            const int row = r0 + t * 16;
#pragma unroll
            for (int j = 0; j < 6; j++) {
                const int col = c0 + j * 8;
                gi[row * ROWP + col]           = acc[t][j][0];
                gi[row * ROWP + col + 1]       = acc[t][j][1];
                gi[(row + 8) * ROWP + col]     = acc[t][j][2];
                gi[(row + 8) * ROWP + col + 1] = acc[t][j][3];
            }
        }
    }
    __syncthreads();

    // ---- fused gate epilogue: 4 threads per row; biases from gmem (L2) ----
    {
        const int row = tid >> 2;
        const int qtr = tid & 3;
        const float* gr = gi + row * ROWP;
        float a = 0.0f;
#pragma unroll 4
        for (int k = 0; k < 32; k++) {
            const int g = qtr * 32 + k;
            const float xr = gr[g] + b_ih[g] + b_hh[g];
            const float xz = gr[128 + g] + b_ih[128 + g] + b_hh[128 + g];
            const float r  = 1.0f / (1.0f + __expf(-xr));
            const float zc = 1.0f / (1.0f + __expf(xz));          // 1 - z
            const float xn = gr[256 + g] + b_ih[256 + g] + r * b_hh[256 + g];
            const float e  = __expf(-2.0f * fabsf(xn));
            float th = __fdividef(1.0f - e, 1.0f + e);
            th = copysignf(th, xn);
            a += lin_w[g] * zc * th;
        }
        a += __shfl_xor_sync(0xffffffffu, a, 1);
        a += __shfl_xor_sync(0xffffffffu, a, 2);
        if (qtr == 0) out[m0 + row] = a + lin_b[0];
    }
}

extern "C" void kernel_launch(void* const* d_in, const int* in_sizes, int n_in,
                              void* d_out, int out_size) {
    const float* x     = (const float*)d_in[0];
    const float* w_ih  = (const float*)d_in[1];
    // d_in[2] = weight_hh: mathematically dead (hidden state is always zero)
    const float* b_ih  = (const float*)d_in[3];
    const float* b_hh  = (const float*)d_in[4];
    const float* lin_w = (const float*)d_in[5];
    const float* lin_b = (const float*)d_in[6];
    float* out = (float*)d_out;

    wconv_kernel<<<192, 256>>>(w_ih);   // 384*1024 / (256*8)

    cudaFuncSetAttribute(ping_head_kernel,
                         cudaFuncAttributeMaxDynamicSharedMemorySize, SMEM_DYN);
    ping_head_kernel<<<1024, 256, SMEM_DYN>>>(x, b_ih, b_hh, lin_w, lin_b, out);
}

// round 13
// speedup vs baseline: 1.1773x; 1.1773x over previous
#include <cuda_runtime.h>
#include <cuda_fp16.h>
#include <cstdint>

// ---------------------------------------------------------------------------
// PingHead on sm_103 (legacy mma.sync path, fp16 operands / fp32 accum).
// gi = x @ W_ih^T : M=65536, N=384, K=1024 ; fused GRU-gate epilogue.
// R13: R11 skeleton (2 CTAs/SM, M_TILE=64, 1m x 8n, K64/128B rows, 2-stage
// ring) with the A copy of chunk kc+1 split across s-steps in 8-reg pieces:
// LDG at s0/s1, STS at s1/s2. Peak extra liveness 8 regs -> no spills.
// B cp.async issued at chunk top (full-chunk flight), WAIT1 as in R11.
// ---------------------------------------------------------------------------

#define M_TILE 64
#define KCHUNKS 16
#define A_ST 8192                            // 64 rows x 128B
#define B_ST 49152                           // 384 rows x 128B
#define STAGE_BYTES (A_ST + B_ST)            // 57344
#define SMEM_DYN (2 * STAGE_BYTES)           // 114688 ; 2 CTAs/SM
#define ROWP 385
// gi (64*385*4 = 98560) fits inside the 114688-byte ring

__device__ __half g_wh[384 * 1024];          // W_ih pre-converted to fp16 (rne)

__device__ __forceinline__ uint32_t smem_u32(const void* p) {
    uint32_t a;
    asm("{ .reg .u64 t; cvta.to.shared.u64 t, %1; cvt.u32.u64 %0, t; }" : "=r"(a) : "l"(p));
    return a;
}

__device__ __forceinline__ void cp_async16(uint32_t dst, const void* src) {
    asm volatile("cp.async.cg.shared.global [%0], [%1], 16;" :: "r"(dst), "l"(src) : "memory");
}
#define CP_COMMIT() asm volatile("cp.async.commit_group;" ::: "memory")
#define CP_WAIT1()  asm volatile("cp.async.wait_group 1;" ::: "memory")
#define CP_WAIT0()  asm volatile("cp.async.wait_group 0;" ::: "memory")

__device__ __forceinline__ void ldsm4(uint32_t* r, uint32_t addr) {
    asm volatile("ldmatrix.sync.aligned.m8n8.x4.shared.b16 {%0,%1,%2,%3}, [%4];"
                 : "=r"(r[0]), "=r"(r[1]), "=r"(r[2]), "=r"(r[3]) : "r"(addr));
}

__device__ __forceinline__ uint32_t pack2h(float a, float b) {
    __half2 h = __floats2half2_rn(a, b);
    return *reinterpret_cast<uint32_t*>(&h);
}

__device__ __forceinline__ void mma_f16(float* d, const uint32_t* a, const uint32_t* b) {
    asm volatile("mma.sync.aligned.m16n8k16.row.col.f32.f16.f16.f32 "
                 "{%0,%1,%2,%3},{%4,%5,%6,%7},{%8,%9},{%0,%1,%2,%3};"
                 : "+f"(d[0]), "+f"(d[1]), "+f"(d[2]), "+f"(d[3])
                 : "r"(a[0]), "r"(a[1]), "r"(a[2]), "r"(a[3]), "r"(b[0]), "r"(b[1]));
}

// --- pre-kernel: W fp32 -> fp16 (rne) ---
__global__ void __launch_bounds__(256) wconv_kernel(const float* __restrict__ w) {
    const int i = (blockIdx.x * 256 + threadIdx.x) * 8;
    const float4 v0 = *reinterpret_cast<const float4*>(w + i);
    const float4 v1 = *reinterpret_cast<const float4*>(w + i + 4);
    uint4 o = make_uint4(pack2h(v0.x, v0.y), pack2h(v0.z, v0.w),
                         pack2h(v1.x, v1.y), pack2h(v1.z, v1.w));
    *reinterpret_cast<uint4*>(g_wh + i) = o;
}

__global__ void __launch_bounds__(256, 2)
ping_head_kernel(const float* __restrict__ x,
                 const float* __restrict__ b_ih,
                 const float* __restrict__ b_hh,
                 const float* __restrict__ lin_w,
                 const float* __restrict__ lin_b,
                 float* __restrict__ out) {
    extern __shared__ char dsm[];

    const int tid = threadIdx.x;
    const int wid = tid >> 5;
    const int lane = tid & 31;
    const int m0 = blockIdx.x * M_TILE;

    const uint32_t sb = smem_u32(dsm);
    char* sb_ptr = dsm;

    const int a_row = tid >> 2;
    const int a_q   = tid & 3;
    const uint32_t a_xr = (uint32_t)((a_row & 7) << 4);

    // B copy for chunk kc (cp.async only)
    auto copy_B = [&](int kc) {
        const int st = kc & 1;
        const int koff = kc * 64;
        const uint32_t bbase = sb + (uint32_t)(st * STAGE_BYTES + A_ST);
#pragma unroll
        for (int ch = 0; ch < 12; ch++) {
            const int bi = tid + ch * 256;
            const int row = bi >> 3, c = bi & 7;
            const uint32_t doff = (uint32_t)(row * 128) +
                                  (((uint32_t)(c * 16)) ^ ((uint32_t)(row & 7) << 4));
            cp_async16(bbase + doff, g_wh + (size_t)row * 1024 + koff + c * 8);
        }
    };
    // A copy for chunk kc (full, prologue only)
    auto copy_A_full = [&](int kc) {
        const int st = kc & 1;
        const int koff = kc * 64;
        const float* asrc = x + (size_t)(m0 + a_row) * 1024 + koff + a_q * 16;
        float4 f0 = *reinterpret_cast<const float4*>(asrc);
        float4 f1 = *reinterpret_cast<const float4*>(asrc + 4);
        float4 f2 = *reinterpret_cast<const float4*>(asrc + 8);
        float4 f3 = *reinterpret_cast<const float4*>(asrc + 12);
        char* sA = sb_ptr + st * STAGE_BYTES;
        uint4 o0 = make_uint4(pack2h(f0.x, f0.y), pack2h(f0.z, f0.w),
                              pack2h(f1.x, f1.y), pack2h(f1.z, f1.w));
        uint4 o1 = make_uint4(pack2h(f2.x, f2.y), pack2h(f2.z, f2.w),
                              pack2h(f3.x, f3.y), pack2h(f3.z, f3.w));
        *reinterpret_cast<uint4*>(sA + a_row * 128 + (((uint32_t)(a_q * 32)) ^ a_xr))      = o0;
        *reinterpret_cast<uint4*>(sA + a_row * 128 + (((uint32_t)(a_q * 32 + 16)) ^ a_xr)) = o1;
    };

    // ---- ldmatrix addressing: 1m x 8n warp grid, warp tile 64m x 48n ----
    const int nb = wid * 48;

    const int ri = lane & 15;
    const uint32_t sega = (uint32_t)((lane >> 4) << 4);
    const uint32_t xpa  = (uint32_t)((ri & 7) << 4);
    const uint32_t a_root = (uint32_t)(ri * 128);

    const int rb = (lane & 7) + (((lane >> 4) & 1) << 3);
    const uint32_t segb = (uint32_t)(((lane >> 3) & 1) << 4);
    const uint32_t xpb  = (uint32_t)((rb & 7) << 4);
    const uint32_t b_root = (uint32_t)A_ST + (uint32_t)((nb + rb) * 128);

    float acc[4][6][4];
#pragma unroll
    for (int t = 0; t < 4; t++)
#pragma unroll
        for (int j = 0; j < 6; j++)
#pragma unroll
            for (int q = 0; q < 4; q++) acc[t][j][q] = 0.0f;

    // prologue: stage 0 complete
    copy_B(0); CP_COMMIT();
    copy_A_full(0);

    for (int kc = 0; kc < KCHUNKS; kc++) {
        const bool more = (kc + 1 < KCHUNKS);
        if (more) { copy_B(kc + 1); CP_COMMIT(); CP_WAIT1(); }
        else      { CP_WAIT0(); }
        __syncthreads();   // B(kc) visible; A(kc) STS (from prev iter) visible

        const uint32_t stb = sb + (uint32_t)((kc & 1) * STAGE_BYTES);
        const float* asrc = x + (size_t)(m0 + a_row) * 1024 + (kc + 1) * 64 + a_q * 16;
        char* sAn = sb_ptr + ((kc + 1) & 1) * STAGE_BYTES;

        float4 f0, f1;   // <= 8 extra live regs at any time

#pragma unroll
        for (int s = 0; s < 4; s++) {
            const uint32_t sbytes = (uint32_t)(s * 32);
            uint32_t af[4][4];
#pragma unroll
            for (int t = 0; t < 4; t++)
                ldsm4(af[t], stb + a_root + (uint32_t)(t * 2048) + ((sbytes + sega) ^ xpa));

            // A(kc+1) piecewise copy: LDG at s0/s1 (after frag loads), STS at s1/s2
            if (more) {
                if (s == 1) {
                    uint4 o = make_uint4(pack2h(f0.x, f0.y), pack2h(f0.z, f0.w),
                                         pack2h(f1.x, f1.y), pack2h(f1.z, f1.w));
                    *reinterpret_cast<uint4*>(sAn + a_row * 128 + (((uint32_t)(a_q * 32)) ^ a_xr)) = o;
                } else if (s == 2) {
                    uint4 o = make_uint4(pack2h(f0.x, f0.y), pack2h(f0.z, f0.w),
                                         pack2h(f1.x, f1.y), pack2h(f1.z, f1.w));
                    *reinterpret_cast<uint4*>(sAn + a_row * 128 + (((uint32_t)(a_q * 32 + 16)) ^ a_xr)) = o;
                }
                if (s == 0) {
                    f0 = *reinterpret_cast<const float4*>(asrc);
                    f1 = *reinterpret_cast<const float4*>(asrc + 4);
                } else if (s == 1) {
                    f0 = *reinterpret_cast<const float4*>(asrc + 8);
                    f1 = *reinterpret_cast<const float4*>(asrc + 12);
                }
            }

#pragma unroll
            for (int jp = 0; jp < 3; jp++) {
                uint32_t bf[4];
                ldsm4(bf, stb + b_root + (uint32_t)(jp * 2048) + ((sbytes + segb) ^ xpb));
#pragma unroll
                for (int t = 0; t < 4; t++) {
                    mma_f16(acc[t][2 * jp],     af[t], bf);
                    mma_f16(acc[t][2 * jp + 1], af[t], bf + 2);
                }
            }
        }
        __syncthreads();   // reads of buf[kc&1] done before its rewrite
    }

    // ---- spill gi to smem (64 x ROWP), reusing the ring ----
    float* gi = reinterpret_cast<float*>(sb_ptr);
    {
        const int r0 = lane >> 2;
        const int c0 = nb + 2 * (lane & 3);
#pragma unroll
        for (int t = 0; t < 4; t++) {
            const int row = r0 + t * 16;
#pragma unroll
            for (int j = 0; j < 6; j++) {
                const int col = c0 + j * 8;
                gi[row * ROWP + col]           = acc[t][j][0];
                gi[row * ROWP + col + 1]       = acc[t][j][1];
                gi[(row + 8) * ROWP + col]     = acc[t][j][2];
                gi[(row + 8) * ROWP + col + 1] = acc[t][j][3];
            }
        }
    }
    __syncthreads();

    // ---- fused gate epilogue: 4 threads per row; biases from gmem (L2) ----
    {
        const int row = tid >> 2;
        const int qtr = tid & 3;
        const float* gr = gi + row * ROWP;
        float a = 0.0f;
#pragma unroll 4
        for (int k = 0; k < 32; k++) {
            const int g = qtr * 32 + k;
            const float xr = gr[g] + b_ih[g] + b_hh[g];
            const float xz = gr[128 + g] + b_ih[128 + g] + b_hh[128 + g];
            const float r  = 1.0f / (1.0f + __expf(-xr));
            const float zc = 1.0f / (1.0f + __expf(xz));          // 1 - z
            const float xn = gr[256 + g] + b_ih[256 + g] + r * b_hh[256 + g];
            const float e  = __expf(-2.0f * fabsf(xn));
            float th = __fdividef(1.0f - e, 1.0f + e);
            th = copysignf(th, xn);
            a += lin_w[g] * zc * th;
        }
        a += __shfl_xor_sync(0xffffffffu, a, 1);
        a += __shfl_xor_sync(0xffffffffu, a, 2);
        if (qtr == 0) out[m0 + row] = a + lin_b[0];
    }
}

extern "C" void kernel_launch(void* const* d_in, const int* in_sizes, int n_in,
                              void* d_out, int out_size) {
    const float* x     = (const float*)d_in[0];
    const float* w_ih  = (const float*)d_in[1];
    // d_in[2] = weight_hh: mathematically dead (hidden state is always zero)
    const float* b_ih  = (const float*)d_in[3];
    const float* b_hh  = (const float*)d_in[4];
    const float* lin_w = (const float*)d_in[5];
    const float* lin_b = (const float*)d_in[6];
    float* out = (float*)d_out;

    wconv_kernel<<<192, 256>>>(w_ih);   // 384*1024 / (256*8)

    cudaFuncSetAttribute(ping_head_kernel,
                         cudaFuncAttributeMaxDynamicSharedMemorySize, SMEM_DYN);
    ping_head_kernel<<<1024, 256, SMEM_DYN>>>(x, b_ih, b_hh, lin_w, lin_b, out);
}

// round 14
// speedup vs baseline: 1.6855x; 1.4317x over previous
#include <cuda_runtime.h>
#include <cuda_fp16.h>
#include <cstdint>

// ---------------------------------------------------------------------------
// PingHead on sm_103 (legacy mma.sync path, fp16 operands / fp32 accum).
// gi = x @ W_ih^T : M=65536, N=384, K=1024 ; fused GRU-gate epilogue.
// R14: M_TILE=64 with 512 threads (acc=48/thread -> ~40 regs of slack),
// 3-stage K64/128B-row ring (172KB, 1 CTA/SM), 2m x 8n warp grid.
// Copy of chunk kc+2 software-pipelined inside MMA(kc): LDG A at top,
// STS after s1 (~1.5k cyc later), cp.async B at top (full-chunk flight).
// One __syncthreads per chunk. Grid 1024 -> 99% tail-wave fill.
// ---------------------------------------------------------------------------

#define M_TILE 64
#define KCHUNKS 16
#define A_ST 8192                            // 64 rows x 128B (fp16)
#define B_ST 49152                           // 384 rows x 128B (fp16)
#define STAGE_BYTES (A_ST + B_ST)            // 57344
#define SMEM_DYN (3 * STAGE_BYTES)           // 172032 ; 1 CTA/SM
#define ROWP 385
// gi (64*385*4 = 98560) fits inside the ring

__device__ __half g_wh[384 * 1024];          // W_ih pre-converted to fp16 (rne)

__device__ __forceinline__ uint32_t smem_u32(const void* p) {
    uint32_t a;
    asm("{ .reg .u64 t; cvta.to.shared.u64 t, %1; cvt.u32.u64 %0, t; }" : "=r"(a) : "l"(p));
    return a;
}

__device__ __forceinline__ void cp_async16(uint32_t dst, const void* src) {
    asm volatile("cp.async.cg.shared.global [%0], [%1], 16;" :: "r"(dst), "l"(src) : "memory");
}
#define CP_COMMIT() asm volatile("cp.async.commit_group;" ::: "memory")
#define CP_WAIT1()  asm volatile("cp.async.wait_group 1;" ::: "memory")
#define CP_WAIT0()  asm volatile("cp.async.wait_group 0;" ::: "memory")

__device__ __forceinline__ void ldsm4(uint32_t* r, uint32_t addr) {
    asm volatile("ldmatrix.sync.aligned.m8n8.x4.shared.b16 {%0,%1,%2,%3}, [%4];"
                 : "=r"(r[0]), "=r"(r[1]), "=r"(r[2]), "=r"(r[3]) : "r"(addr));
}

__device__ __forceinline__ uint32_t pack2h(float a, float b) {
    __half2 h = __floats2half2_rn(a, b);
    return *reinterpret_cast<uint32_t*>(&h);
}

__device__ __forceinline__ void mma_f16(float* d, const uint32_t* a, const uint32_t* b) {
    asm volatile("mma.sync.aligned.m16n8k16.row.col.f32.f16.f16.f32 "
                 "{%0,%1,%2,%3},{%4,%5,%6,%7},{%8,%9},{%0,%1,%2,%3};"
                 : "+f"(d[0]), "+f"(d[1]), "+f"(d[2]), "+f"(d[3])
                 : "r"(a[0]), "r"(a[1]), "r"(a[2]), "r"(a[3]), "r"(b[0]), "r"(b[1]));
}

// --- pre-kernel: W fp32 -> fp16 (rne) ---
__global__ void __launch_bounds__(256) wconv_kernel(const float* __restrict__ w) {
    const int i = (blockIdx.x * 256 + threadIdx.x) * 8;
    const float4 v0 = *reinterpret_cast<const float4*>(w + i);
    const float4 v1 = *reinterpret_cast<const float4*>(w + i + 4);
    uint4 o = make_uint4(pack2h(v0.x, v0.y), pack2h(v0.z, v0.w),
                         pack2h(v1.x, v1.y), pack2h(v1.z, v1.w));
    *reinterpret_cast<uint4*>(g_wh + i) = o;
}

__global__ void __launch_bounds__(512, 1)
ping_head_kernel(const float* __restrict__ x,
                 const float* __restrict__ b_ih,
                 const float* __restrict__ b_hh,
                 const float* __restrict__ lin_w,
                 const float* __restrict__ lin_b,
                 float* __restrict__ out) {
    extern __shared__ char dsm[];

    const int tid = threadIdx.x;
    const int wid = tid >> 5;
    const int lane = tid & 31;
    const int m0 = blockIdx.x * M_TILE;

    const uint32_t sb = smem_u32(dsm);
    char* sb_ptr = dsm;

    // A copy mapping: 64 rows x 64 f32 per chunk / 512 thr = 8 floats/thread
    const int a_row = tid >> 3;              // 0..63
    const int a_q   = tid & 7;               // 0..7 (16B fp16 chunk index)
    const uint32_t a_xr = (uint32_t)((a_row & 7) << 4);

    auto cpB = [&](int kc) {                 // 3072 x 16B / 512 = 6 per thread
        const int st = kc % 3;
        const int koff = kc * 64;
        const uint32_t bbase = sb + (uint32_t)(st * STAGE_BYTES + A_ST);
#pragma unroll
        for (int ch = 0; ch < 6; ch++) {
            const int bi = tid + ch * 512;
            const int row = bi >> 3, c = bi & 7;
            const uint32_t doff = (uint32_t)(row * 128) +
                                  (((uint32_t)(c * 16)) ^ ((uint32_t)(row & 7) << 4));
            cp_async16(bbase + doff, g_wh + (size_t)row * 1024 + koff + c * 8);
        }
    };
    auto copy_A_full = [&](int kc) {         // prologue only
        const int st = kc % 3;
        const float* asrc = x + (size_t)(m0 + a_row) * 1024 + kc * 64 + a_q * 8;
        const float4 f0 = *reinterpret_cast<const float4*>(asrc);
        const float4 f1 = *reinterpret_cast<const float4*>(asrc + 4);
        uint4 o = make_uint4(pack2h(f0.x, f0.y), pack2h(f0.z, f0.w),
                             pack2h(f1.x, f1.y), pack2h(f1.z, f1.w));
        *reinterpret_cast<uint4*>(sb_ptr + st * STAGE_BYTES + a_row * 128 +
                                  (((uint32_t)(a_q * 16)) ^ a_xr)) = o;
    };

    // ---- ldmatrix addressing: 2m x 8n warp grid, warp tile 32m x 48n ----
    const int warp_m = wid >> 3;             // 0..1
    const int warp_n = wid & 7;              // 0..7
    const int mb = warp_m * 32;
    const int nb = warp_n * 48;

    const int ri = lane & 15;
    const uint32_t sega = (uint32_t)((lane >> 4) << 4);
    const uint32_t xpa  = (uint32_t)((ri & 7) << 4);
    const uint32_t a_root = (uint32_t)((mb + ri) * 128);

    const int rb = (lane & 7) + (((lane >> 4) & 1) << 3);
    const uint32_t segb = (uint32_t)(((lane >> 3) & 1) << 4);
    const uint32_t xpb  = (uint32_t)((rb & 7) << 4);
    const uint32_t b_root = (uint32_t)A_ST + (uint32_t)((nb + rb) * 128);

    float acc[2][6][4];
#pragma unroll
    for (int t = 0; t < 2; t++)
#pragma unroll
        for (int j = 0; j < 6; j++)
#pragma unroll
            for (int q = 0; q < 4; q++) acc[t][j][q] = 0.0f;

    // prologue: stages 0 and 1 complete (two groups pending)
    copy_A_full(0); cpB(0); CP_COMMIT();
    copy_A_full(1); cpB(1); CP_COMMIT();

    for (int kc = 0; kc < KCHUNKS; kc++) {
        if (kc < KCHUNKS - 2) CP_WAIT1(); else CP_WAIT0();
        __syncthreads();   // stage kc ready; prior reads of stage (kc+2)%3 done

        const uint32_t stb = sb + (uint32_t)((kc % 3) * STAGE_BYTES);
        const bool more = (kc + 2 < KCHUNKS);

        // ---- start copy of chunk kc+2: A LDG + B cp.async (flight = full chunk)
        float4 f0, f1;     // 8 staging regs, live until after s1
        if (more) {
            const float* asrc = x + (size_t)(m0 + a_row) * 1024 + (kc + 2) * 64 + a_q * 8;
            f0 = *reinterpret_cast<const float4*>(asrc);
            f1 = *reinterpret_cast<const float4*>(asrc + 4);
            cpB(kc + 2);
            CP_COMMIT();
        }

        // ---- MMA s = 0, 1 ----
#pragma unroll
        for (int s = 0; s < 2; s++) {
            const uint32_t sbytes = (uint32_t)(s * 32);
            uint32_t af[2][4];
            ldsm4(af[0], stb + a_root + ((sbytes + sega) ^ xpa));
            ldsm4(af[1], stb + a_root + 2048u + ((sbytes + sega) ^ xpa));
#pragma unroll
            for (int jp = 0; jp < 3; jp++) {
                uint32_t bf[4];
                ldsm4(bf, stb + b_root + (uint32_t)(jp * 2048) + ((sbytes + segb) ^ xpb));
                mma_f16(acc[0][2 * jp],     af[0], bf);
                mma_f16(acc[0][2 * jp + 1], af[0], bf + 2);
                mma_f16(acc[1][2 * jp],     af[1], bf);
                mma_f16(acc[1][2 * jp + 1], af[1], bf + 2);
            }
        }

        // ---- STS A(kc+2): LDG has had ~1.5k cycles to return ----
        if (more) {
            uint4 o = make_uint4(pack2h(f0.x, f0.y), pack2h(f0.z, f0.w),
                                 pack2h(f1.x, f1.y), pack2h(f1.z, f1.w));
            *reinterpret_cast<uint4*>(sb_ptr + ((kc + 2) % 3) * STAGE_BYTES + a_row * 128 +
                                      (((uint32_t)(a_q * 16)) ^ a_xr)) = o;
        }

        // ---- MMA s = 2, 3 ----
#pragma unroll
        for (int s = 2; s < 4; s++) {
            const uint32_t sbytes = (uint32_t)(s * 32);
            uint32_t af[2][4];
            ldsm4(af[0], stb + a_root + ((sbytes + sega) ^ xpa));
            ldsm4(af[1], stb + a_root + 2048u + ((sbytes + sega) ^ xpa));
#pragma unroll
            for (int jp = 0; jp < 3; jp++) {
                uint32_t bf[4];
                ldsm4(bf, stb + b_root + (uint32_t)(jp * 2048) + ((sbytes + segb) ^ xpb));
                mma_f16(acc[0][2 * jp],     af[0], bf);
                mma_f16(acc[0][2 * jp + 1], af[0], bf + 2);
                mma_f16(acc[1][2 * jp],     af[1], bf);
                mma_f16(acc[1][2 * jp + 1], af[1], bf + 2);
            }
        }
    }

    __syncthreads();

    // ---- spill gi to smem (64 x ROWP), reusing the ring ----
    float* gi = reinterpret_cast<float*>(sb_ptr);
    {
        const int r0 = mb + (lane >> 2);
        const int c0 = nb + 2 * (lane & 3);
#pragma unroll
        for (int t = 0; t < 2; t++) {
            const int row = r0 + t * 16;
#pragma unroll
            for (int j = 0; j < 6; j++) {
                const int col = c0 + j * 8;
                gi[row * ROWP + col]           = acc[t][j][0];
                gi[row * ROWP + col + 1]       = acc[t][j][1];
                gi[(row + 8) * ROWP + col]     = acc[t][j][2];
                gi[(row + 8) * ROWP + col + 1] = acc[t][j][3];
            }
        }
    }
    __syncthreads();

    // ---- fused gate epilogue: 8 threads per row; biases from gmem (L2) ----
    {
        const int row = tid >> 3;
        const int oct = tid & 7;
        const float* gr = gi + row * ROWP;
        float a = 0.0f;
#pragma unroll 4
        for (int k = 0; k < 16; k++) {
            const int g = oct * 16 + k;
            const float xr = gr[g] + b_ih[g] + b_hh[g];
            const float xz = gr[128 + g] + b_ih[128 + g] + b_hh[128 + g];
            const float r  = 1.0f / (1.0f + __expf(-xr));
            const float zc = 1.0f / (1.0f + __expf(xz));          // 1 - z
            const float xn = gr[256 + g] + b_ih[256 + g] + r * b_hh[256 + g];
            const float e  = __expf(-2.0f * fabsf(xn));
            float th = __fdividef(1.0f - e, 1.0f + e);
            th = copysignf(th, xn);
            a += lin_w[g] * zc * th;
        }
        a += __shfl_xor_sync(0xffffffffu, a, 1);
        a += __shfl_xor_sync(0xffffffffu, a, 2);
        a += __shfl_xor_sync(0xffffffffu, a, 4);
        if (oct == 0) out[m0 + row] = a + lin_b[0];
    }
}

extern "C" void kernel_launch(void* const* d_in, const int* in_sizes, int n_in,
                              void* d_out, int out_size) {
    const float* x     = (const float*)d_in[0];
    const float* w_ih  = (const float*)d_in[1];
    // d_in[2] = weight_hh: mathematically dead (hidden state is always zero)
    const float* b_ih  = (const float*)d_in[3];
    const float* b_hh  = (const float*)d_in[4];
    const float* lin_w = (const float*)d_in[5];
    const float* lin_b = (const float*)d_in[6];
    float* out = (float*)d_out;

    wconv_kernel<<<192, 256>>>(w_ih);   // 384*1024 / (256*8)

    cudaFuncSetAttribute(ping_head_kernel,
                         cudaFuncAttributeMaxDynamicSharedMemorySize, SMEM_DYN);
    ping_head_kernel<<<1024, 512, SMEM_DYN>>>(x, b_ih, b_hh, lin_w, lin_b, out);
}